// round 2
// baseline (speedup 1.0000x reference)
#include <cuda_runtime.h>
#include <cstdint>
#include <cstdlib>

#define T_DIM 512
#define NC 65
#define NTT 64
#define KV 128
#define SS 192
#define D_DIM 256

#define LOG2E_F 1.4426950408889634f
#define LN2_F   0.6931471805599453f
#define KD_F (LOG2E_F / 128.0f)        // dyn: ct = n/128 -> log2 domain
#define KS_F (LOG2E_F * 0.15625f)      // sta: logit = n*20/128

__device__ __forceinline__ float ex2f(float x) {
    float y; asm("ex2.approx.ftz.f32 %0, %1;" : "=f"(y) : "f"(x)); return y;
}

__global__ __launch_bounds__(288, 7)
void cg_kernel(const int* __restrict__ cur_tar, const int* __restrict__ cnc_loc,
               const int* __restrict__ sta_loc, const int* __restrict__ ttn_loc,
               const int* __restrict__ voc_loc, const float* __restrict__ sta_emb,
               const float* __restrict__ ttn_emb, float* __restrict__ out)
{
    __shared__ uint32_t s_w[SS * 8];      // packed abs(pos) | sign<<31
    __shared__ float    s_afd[NTT * 8];   // A[s,p] * KD   (s < 64)
    __shared__ float    s_afs[KV * 8];    // A[64+k,p] * KS
    __shared__ float    s_pe[NTT];        // p_eu
    __shared__ float    s_eu[NTT];
    __shared__ float    s_semb[D_DIM];
    __shared__ float    s_pa[8];
    __shared__ float    s_c1;

    const int b    = blockIdx.x;
    const int t    = b >> 1;
    const int half = b & 1;
    const int c0   = half ? 33 : 0;
    const int nc   = half ? 32 : 33;
    const int tid  = threadIdx.x;

    // ---------------- Phase A: pos words + A*K tables ----------------
    if (tid < SS) {
        const int s = tid;
        const int* sl   = sta_loc + (size_t)t * 8;
        const int* prow = (s < NTT) ? (ttn_loc + ((size_t)t * NTT + s) * 8)
                                    : (voc_loc + ((size_t)t * KV + (s - NTT)) * 8);
        int nsp[8];
        int sumn = 0;
        #pragma unroll
        for (int p = 0; p < 8; p++) {
            int v  = prow[p];
            int sv = sl[p];
            uint32_t av = (uint32_t)abs(v);
            uint32_t as = (uint32_t)abs(sv);
            uint32_t x  = av ^ as;                 // <= 0xFFFF
            int flo = 31 - __clz(x + 1u);          // bitlength-1, in [0,16]
            int n   = 15 - flo;
            if ((v < 0) != (sv < 0)) n = -n;
            nsp[p] = n; sumn += n;
            s_w[s * 8 + p] = av | ((v < 0) ? 0x80000000u : 0u);
        }
        #pragma unroll
        for (int p = 0; p < 8; p++) {
            float An = (float)(sumn - nsp[p]);
            if (s < NTT) s_afd[s * 8 + p] = An * KD_F;
            else         s_afs[(s - NTT) * 8 + p] = An * KS_F;
        }
    }
    for (int i = tid; i < D_DIM; i += 288) s_semb[i] = sta_emb[(size_t)t * D_DIM + i];
    __syncthreads();

    // ---------------- Phase B: eu logits (dot products) ----------------
    {
        const int wid = tid >> 5, lane = tid & 31;
        const float4* sb = (const float4*)s_semb;
        float4 b0 = sb[lane], b1 = sb[lane + 32];
        for (int s = wid; s < NTT; s += 9) {
            const float4* ep = (const float4*)(ttn_emb + ((size_t)t * NTT + s) * D_DIM);
            float4 a0 = ep[lane], a1 = ep[lane + 32];
            float d = a0.x * b0.x + a0.y * b0.y + a0.z * b0.z + a0.w * b0.w
                    + a1.x * b1.x + a1.y * b1.y + a1.z * b1.z + a1.w * b1.w;
            #pragma unroll
            for (int off = 16; off; off >>= 1) d += __shfl_xor_sync(0xffffffffu, d, off);
            if (lane == 0) s_eu[s] = d;
        }
    }
    __syncthreads();

    // ---------------- Phase C: eu softmax (warp 0) ----------------
    if (tid < 32) {
        float e0 = s_eu[tid], e1 = s_eu[tid + 32];
        float mx = fmaxf(e0, e1);
        #pragma unroll
        for (int off = 16; off; off >>= 1) mx = fmaxf(mx, __shfl_xor_sync(0xffffffffu, mx, off));
        float z0 = e0 - mx, z1 = e1 - mx;
        float p0 = ex2f(z0 * LOG2E_F), p1 = ex2f(z1 * LOG2E_F);
        float Z = p0 + p1, W = p0 * z0 + p1 * z1;
        #pragma unroll
        for (int off = 16; off; off >>= 1) {
            Z += __shfl_xor_sync(0xffffffffu, Z, off);
            W += __shfl_xor_sync(0xffffffffu, W, off);
        }
        float rZ = 1.0f / Z;
        s_pe[tid] = p0 * rZ;
        s_pe[tid + 32] = p1 * rZ;
        if (tid == 0) s_c1 = W * rZ - __logf(Z);   // C1 = sum p*lp
    }
    __syncthreads();

    // ---------------- Phase D: PA[p] = ln2 * sum_s pe[s]*Afd[s,p] ----------------
    if (tid < 8) {
        float a = 0.f;
        #pragma unroll 8
        for (int s = 0; s < NTT; s++) a = fmaf(s_pe[s], s_afd[s * 8 + tid], a);
        s_pa[tid] = a * LN2_F;
    }
    __syncthreads();

    // ---------------- Phase E: main per-(c,p) loops ----------------
    if (tid < nc * 8) {
        const int c = c0 + (tid >> 3);
        const int p = tid & 7;
        const int cv = cnc_loc[((size_t)t * NC + c) * 8 + p];
        const uint32_t wc = (uint32_t)abs(cv) | ((cv < 0) ? 0x80000000u : 0u);

        // dyn: s in [0,64)
        float se = 0.f, acc = 0.f;
        #pragma unroll 4
        for (int s = 0; s < NTT; s++) {
            uint32_t x = s_w[s * 8 + p] ^ wc;
            int flo = 31 - __clz((x & 0xFFFFu) + 1u);
            int m = ((int)x) >> 31;                 // 0 or -1 (sign product)
            int u = (15 - flo + m) ^ m;             // signed numerator of cos_cp*16
            float uf = (float)u;
            se += ex2f(fmaf(uf, KD_F, s_afd[s * 8 + p]));
            acc = fmaf(s_pe[s], uf, acc);
        }
        float ldd = s_c1 - s_pa[p] - acc * 0.0078125f + __logf(se);
        out[((size_t)t * NC + c) * 8 + p] = ldd;

        // sta: k in [0,128)
        float se2 = 0.f;
        #pragma unroll 4
        for (int k = 0; k < KV; k++) {
            uint32_t x = s_w[(NTT + k) * 8 + p] ^ wc;
            int flo = 31 - __clz((x & 0xFFFFu) + 1u);
            int m = ((int)x) >> 31;
            int u = (15 - flo + m) ^ m;
            se2 += ex2f(fmaf((float)u, KS_F, s_afs[k * 8 + p]));
        }
        const int tar = cur_tar[t];
        float argt;
        {
            uint32_t x = s_w[(NTT + tar) * 8 + p] ^ wc;
            int flo = 31 - __clz((x & 0xFFFFu) + 1u);
            int m = ((int)x) >> 31;
            int u = (15 - flo + m) ^ m;
            argt = fmaf((float)u, KS_F, s_afs[tar * 8 + p]);
        }
        float lds_v = __logf(se2) - LN2_F * argt;
        out[(size_t)T_DIM * NC * 8 + ((size_t)t * NC + c) * 8 + p] = lds_v;
    }
}

extern "C" void kernel_launch(void* const* d_in, const int* in_sizes, int n_in,
                              void* d_out, int out_size)
{
    const int*   cur_tar = (const int*)d_in[0];
    const int*   cnc_loc = (const int*)d_in[1];
    const int*   sta_loc = (const int*)d_in[2];
    const int*   ttn_loc = (const int*)d_in[3];
    const int*   voc_loc = (const int*)d_in[4];
    const float* sta_emb = (const float*)d_in[5];
    const float* ttn_emb = (const float*)d_in[6];
    // d_in[7] = voc_emb: unused by the math (eu_val[:, 64:] is discarded)
    float* out = (float*)d_out;

    cg_kernel<<<1024, 288>>>(cur_tar, cnc_loc, sta_loc, ttn_loc, voc_loc,
                             sta_emb, ttn_emb, out);
}